// round 7
// baseline (speedup 1.0000x reference)
#include <cuda_runtime.h>
#include <math.h>
#include <stdint.h>

#define NB 128
#define NA_MAX 500000

// Scratch (allocation-free: __device__ globals)
__device__ float  g_cell[NB * 9];    // cell + cell @ sym (written by atom block 0)
__device__ float4 g_atom[NA_MAX];    // strained pos + batch (bit-cast)
__device__ int    g_is64;            // 1 if edge_index/batch are int64

// ---------------------------------------------------------------------------
// Kernel 1: per-atom strained position packed with batch into float4.
// Block 0 additionally publishes g_cell and g_is64 for the edge kernel.
// ---------------------------------------------------------------------------
__global__ void __launch_bounds__(256) atom_kernel(
        const float* __restrict__ pos,
        const void*  __restrict__ batch,
        const void*  __restrict__ eidx,
        const float* __restrict__ strain,
        const float* __restrict__ cell,
        int n_atoms) {
    __shared__ float sS[NB * 9];
    __shared__ int s_is64;
    int tid = threadIdx.x;

    // dtype detection: int64 indices (< 2^31, nonneg) have all-zero odd words.
    if (tid == 0) {
        const unsigned* w = (const unsigned*)eidx;
        unsigned any = 0;
#pragma unroll
        for (int i = 0; i < 64; i++) any |= w[2 * i + 1];
        s_is64 = (any == 0u) ? 1 : 0;
    }
    // sym = 0.5 * (strain + strain^T)
    for (int i = tid; i < NB * 9; i += blockDim.x) {
        int b = i / 9, r = (i % 9) / 3, c = i % 3;
        sS[i] = 0.5f * (strain[b * 9 + r * 3 + c] + strain[b * 9 + c * 3 + r]);
    }
    __syncthreads();

    if (blockIdx.x == 0) {
        // cell_new = cell + cell @ sym  (published for edge kernel)
        for (int i = tid; i < NB * 9; i += blockDim.x) {
            int b = i / 9, r = (i % 9) / 3, c = i % 3;
            float acc = cell[i];
#pragma unroll
            for (int k = 0; k < 3; k++)
                acc += cell[b * 9 + r * 3 + k] * sS[b * 9 + k * 3 + c];
            g_cell[i] = acc;
        }
        if (tid == 0) g_is64 = s_is64;
    }

    int i = blockIdx.x * blockDim.x + tid;
    if (i >= n_atoms) return;

    int b = s_is64 ? (int)((const long long*)batch)[i]
                   : ((const int*)batch)[i];

    float px = pos[3 * i], py = pos[3 * i + 1], pz = pos[3 * i + 2];
    const float* S = &sS[b * 9];
    float nx = px + px * S[0] + py * S[3] + pz * S[6];
    float ny = py + px * S[1] + py * S[4] + pz * S[7];
    float nz = pz + px * S[2] + py * S[5] + pz * S[8];
    g_atom[i] = make_float4(nx, ny, nz, __int_as_float(b));
}

// ---------------------------------------------------------------------------
// Kernel 2: edge vectors + lengths. Exact R5 body (4 edges/thread, vectorized
// .cs streams, scalar smem cell lookup, scalars only) + 5 blocks/SM cap.
// ---------------------------------------------------------------------------
__global__ void __launch_bounds__(256, 5) edge_kernel(
        const void*  __restrict__ eidx,
        const float* __restrict__ cshift,
        float*       __restrict__ out,
        long long E) {
    __shared__ float sC[NB * 9];
    __shared__ int sI;
    if (threadIdx.x == 0) sI = g_is64;
    for (int i = threadIdx.x; i < NB * 9; i += blockDim.x)
        sC[i] = g_cell[i];
    __syncthreads();

    long long t  = (long long)blockIdx.x * blockDim.x + threadIdx.x;
    long long e0 = t << 2;
    if (e0 >= E) return;

    if ((E & 3LL) == 0LL) {
        int s0i, s1i, s2i, s3i, d0i, d1i, d2i, d3i;
        if (sI) {
            const longlong2* ps = (const longlong2*)eidx;
            longlong2 a = __ldcs(&ps[2 * t]);
            longlong2 b = __ldcs(&ps[2 * t + 1]);
            const longlong2* pd = (const longlong2*)((const long long*)eidx + E);
            longlong2 c = __ldcs(&pd[2 * t]);
            longlong2 dd = __ldcs(&pd[2 * t + 1]);
            s0i = (int)a.x; s1i = (int)a.y; s2i = (int)b.x; s3i = (int)b.y;
            d0i = (int)c.x; d1i = (int)c.y; d2i = (int)dd.x; d3i = (int)dd.y;
        } else {
            const int4* ps = (const int4*)eidx;
            int4 a = __ldcs(&ps[t]);
            const int4* pd = (const int4*)((const int*)eidx + E);
            int4 c = __ldcs(&pd[t]);
            s0i = a.x; s1i = a.y; s2i = a.z; s3i = a.w;
            d0i = c.x; d1i = c.y; d2i = c.z; d3i = c.w;
        }

        // 8 independent 16B gathers in flight (L2-resident table)
        float4 A0 = __ldg(&g_atom[s0i]);
        float4 A1 = __ldg(&g_atom[s1i]);
        float4 A2 = __ldg(&g_atom[s2i]);
        float4 A3 = __ldg(&g_atom[s3i]);
        float4 D0 = __ldg(&g_atom[d0i]);
        float4 D1 = __ldg(&g_atom[d1i]);
        float4 D2 = __ldg(&g_atom[d2i]);
        float4 D3 = __ldg(&g_atom[d3i]);

        const float4* cs4 = (const float4*)cshift;
        float4 c0 = __ldcs(&cs4[3 * t]);
        float4 c1 = __ldcs(&cs4[3 * t + 1]);
        float4 c2 = __ldcs(&cs4[3 * t + 2]);

        // edge 0
        const float* C = &sC[__float_as_int(A0.w) * 9];
        float vx0 = D0.x - A0.x + c0.x * C[0] + c0.y * C[3] + c0.z * C[6];
        float vy0 = D0.y - A0.y + c0.x * C[1] + c0.y * C[4] + c0.z * C[7];
        float vz0 = D0.z - A0.z + c0.x * C[2] + c0.y * C[5] + c0.z * C[8];
        float ln0 = sqrtf(vx0 * vx0 + vy0 * vy0 + vz0 * vz0);
        // edge 1
        C = &sC[__float_as_int(A1.w) * 9];
        float vx1 = D1.x - A1.x + c0.w * C[0] + c1.x * C[3] + c1.y * C[6];
        float vy1 = D1.y - A1.y + c0.w * C[1] + c1.x * C[4] + c1.y * C[7];
        float vz1 = D1.z - A1.z + c0.w * C[2] + c1.x * C[5] + c1.y * C[8];
        float ln1 = sqrtf(vx1 * vx1 + vy1 * vy1 + vz1 * vz1);
        // edge 2
        C = &sC[__float_as_int(A2.w) * 9];
        float vx2 = D2.x - A2.x + c1.z * C[0] + c1.w * C[3] + c2.x * C[6];
        float vy2 = D2.y - A2.y + c1.z * C[1] + c1.w * C[4] + c2.x * C[7];
        float vz2 = D2.z - A2.z + c1.z * C[2] + c1.w * C[5] + c2.x * C[8];
        float ln2 = sqrtf(vx2 * vx2 + vy2 * vy2 + vz2 * vz2);
        // edge 3
        C = &sC[__float_as_int(A3.w) * 9];
        float vx3 = D3.x - A3.x + c2.y * C[0] + c2.z * C[3] + c2.w * C[6];
        float vy3 = D3.y - A3.y + c2.y * C[1] + c2.z * C[4] + c2.w * C[7];
        float vz3 = D3.z - A3.z + c2.y * C[2] + c2.z * C[5] + c2.w * C[8];
        float ln3 = sqrtf(vx3 * vx3 + vy3 * vy3 + vz3 * vz3);

        float4* ov = (float4*)out;
        __stcs(&ov[3 * t],     make_float4(vx0, vy0, vz0, vx1));
        __stcs(&ov[3 * t + 1], make_float4(vy1, vz1, vx2, vy2));
        __stcs(&ov[3 * t + 2], make_float4(vz2, vx3, vy3, vz3));
        float4* ol = (float4*)(out + 3 * E);
        __stcs(&ol[t], make_float4(ln0, ln1, ln2, ln3));
    } else {
        // scalar fallback (E not divisible by 4)
        for (long long e = e0; e < e0 + 4 && e < E; e++) {
            long long src, dst;
            if (sI) {
                const long long* p = (const long long*)eidx;
                src = p[e]; dst = p[E + e];
            } else {
                const int* p = (const int*)eidx;
                src = p[e]; dst = p[E + e];
            }
            float4 as = __ldg(&g_atom[src]);
            float4 ad = __ldg(&g_atom[dst]);
            const float* C = &sC[__float_as_int(as.w) * 9];
            float s0 = cshift[3 * e], s1 = cshift[3 * e + 1], s2 = cshift[3 * e + 2];
            float ex = ad.x - as.x + s0 * C[0] + s1 * C[3] + s2 * C[6];
            float ey = ad.y - as.y + s0 * C[1] + s1 * C[4] + s2 * C[7];
            float ez = ad.z - as.z + s0 * C[2] + s1 * C[5] + s2 * C[8];
            out[3 * e] = ex; out[3 * e + 1] = ey; out[3 * e + 2] = ez;
            out[3 * E + e] = sqrtf(ex * ex + ey * ey + ez * ez);
        }
    }
}

// ---------------------------------------------------------------------------
extern "C" void kernel_launch(void* const* d_in, const int* in_sizes, int n_in,
                              void* d_out, int out_size) {
    const float* pos    = (const float*)d_in[0];   // [N_ATOMS, 3]
    const float* cell   = (const float*)d_in[1];   // [NB, 3, 3]
    const float* cshift = (const float*)d_in[2];   // [E, 3]
    const void*  eidx   = d_in[3];                 // [2, E] int32 or int64
    const void*  batch  = d_in[4];                 // [N_ATOMS] int32 or int64
    const float* strain = (const float*)d_in[5];   // [NB, 3, 3]

    int n_atoms = in_sizes[0] / 3;
    long long E = (long long)in_sizes[3] / 2;

    int ablocks = (n_atoms + 255) / 256;
    atom_kernel<<<ablocks, 256>>>(pos, batch, eidx, strain, cell, n_atoms);

    long long egroups = (E + 3) / 4;
    int eblocks = (int)((egroups + 255) / 256);
    edge_kernel<<<eblocks, 256>>>(eidx, cshift, (float*)d_out, E);
}

// round 8
// speedup vs baseline: 1.7934x; 1.7934x over previous
#include <cuda_runtime.h>
#include <math.h>
#include <stdint.h>

#define NB 128
#define NA_MAX 500000

// Scratch (allocation-free: __device__ globals)
__device__ float  g_cell[NB * 9];    // cell + cell @ sym (written by atom block 0)
__device__ float4 g_atom[NA_MAX];    // strained pos + batch (bit-cast)
__device__ int    g_is64;            // 1 if edge_index/batch are int64

// ---------------------------------------------------------------------------
// Kernel 1: per-atom strained position packed with batch into float4.
// Block 0 additionally publishes g_cell and g_is64 for the edge kernel.
// ---------------------------------------------------------------------------
__global__ void __launch_bounds__(256) atom_kernel(
        const float* __restrict__ pos,
        const void*  __restrict__ batch,
        const void*  __restrict__ eidx,
        const float* __restrict__ strain,
        const float* __restrict__ cell,
        int n_atoms) {
    __shared__ float sS[NB * 9];
    __shared__ int s_is64;
    int tid = threadIdx.x;

    // dtype detection: int64 indices (< 2^31, nonneg) have all-zero odd words.
    if (tid == 0) {
        const unsigned* w = (const unsigned*)eidx;
        unsigned any = 0;
#pragma unroll
        for (int i = 0; i < 64; i++) any |= w[2 * i + 1];
        s_is64 = (any == 0u) ? 1 : 0;
    }
    // sym = 0.5 * (strain + strain^T)
    for (int i = tid; i < NB * 9; i += blockDim.x) {
        int b = i / 9, r = (i % 9) / 3, c = i % 3;
        sS[i] = 0.5f * (strain[b * 9 + r * 3 + c] + strain[b * 9 + c * 3 + r]);
    }
    __syncthreads();

    if (blockIdx.x == 0) {
        // cell_new = cell + cell @ sym  (published for edge kernel)
        for (int i = tid; i < NB * 9; i += blockDim.x) {
            int b = i / 9, r = (i % 9) / 3, c = i % 3;
            float acc = cell[i];
#pragma unroll
            for (int k = 0; k < 3; k++)
                acc += cell[b * 9 + r * 3 + k] * sS[b * 9 + k * 3 + c];
            g_cell[i] = acc;
        }
        if (tid == 0) g_is64 = s_is64;
    }

    int i = blockIdx.x * blockDim.x + tid;
    if (i >= n_atoms) return;

    int b = s_is64 ? (int)__ldcs(&((const long long*)batch)[i])
                   : __ldcs(&((const int*)batch)[i]);

    float px = __ldcs(&pos[3 * i]);
    float py = __ldcs(&pos[3 * i + 1]);
    float pz = __ldcs(&pos[3 * i + 2]);
    const float* S = &sS[b * 9];
    float nx = px + px * S[0] + py * S[3] + pz * S[6];
    float ny = py + px * S[1] + py * S[4] + pz * S[7];
    float nz = pz + px * S[2] + py * S[5] + pz * S[8];
    g_atom[i] = make_float4(nx, ny, nz, __int_as_float(b));
}

// ---------------------------------------------------------------------------
// Kernel 2: edge vectors + lengths. Proven-best R5 configuration: 4 edges per
// thread, vectorized .cs streams, scalar smem cell lookup, scalars only,
// NO register cap (body needs 54 regs; any cap spills float4 operands).
// ---------------------------------------------------------------------------
__global__ void __launch_bounds__(256) edge_kernel(
        const void*  __restrict__ eidx,
        const float* __restrict__ cshift,
        float*       __restrict__ out,
        long long E) {
    __shared__ float sC[NB * 9];
    __shared__ int sI;
    if (threadIdx.x == 0) sI = g_is64;
    for (int i = threadIdx.x; i < NB * 9; i += blockDim.x)
        sC[i] = g_cell[i];
    __syncthreads();

    long long t  = (long long)blockIdx.x * blockDim.x + threadIdx.x;
    long long e0 = t << 2;
    if (e0 >= E) return;

    if ((E & 3LL) == 0LL) {
        int s0i, s1i, s2i, s3i, d0i, d1i, d2i, d3i;
        if (sI) {
            const longlong2* ps = (const longlong2*)eidx;
            longlong2 a = __ldcs(&ps[2 * t]);
            longlong2 b = __ldcs(&ps[2 * t + 1]);
            const longlong2* pd = (const longlong2*)((const long long*)eidx + E);
            longlong2 c = __ldcs(&pd[2 * t]);
            longlong2 dd = __ldcs(&pd[2 * t + 1]);
            s0i = (int)a.x; s1i = (int)a.y; s2i = (int)b.x; s3i = (int)b.y;
            d0i = (int)c.x; d1i = (int)c.y; d2i = (int)dd.x; d3i = (int)dd.y;
        } else {
            const int4* ps = (const int4*)eidx;
            int4 a = __ldcs(&ps[t]);
            const int4* pd = (const int4*)((const int*)eidx + E);
            int4 c = __ldcs(&pd[t]);
            s0i = a.x; s1i = a.y; s2i = a.z; s3i = a.w;
            d0i = c.x; d1i = c.y; d2i = c.z; d3i = c.w;
        }

        // 8 independent 16B gathers in flight (L2-resident table)
        float4 A0 = __ldg(&g_atom[s0i]);
        float4 A1 = __ldg(&g_atom[s1i]);
        float4 A2 = __ldg(&g_atom[s2i]);
        float4 A3 = __ldg(&g_atom[s3i]);
        float4 D0 = __ldg(&g_atom[d0i]);
        float4 D1 = __ldg(&g_atom[d1i]);
        float4 D2 = __ldg(&g_atom[d2i]);
        float4 D3 = __ldg(&g_atom[d3i]);

        const float4* cs4 = (const float4*)cshift;
        float4 c0 = __ldcs(&cs4[3 * t]);
        float4 c1 = __ldcs(&cs4[3 * t + 1]);
        float4 c2 = __ldcs(&cs4[3 * t + 2]);

        // edge 0
        const float* C = &sC[__float_as_int(A0.w) * 9];
        float vx0 = D0.x - A0.x + c0.x * C[0] + c0.y * C[3] + c0.z * C[6];
        float vy0 = D0.y - A0.y + c0.x * C[1] + c0.y * C[4] + c0.z * C[7];
        float vz0 = D0.z - A0.z + c0.x * C[2] + c0.y * C[5] + c0.z * C[8];
        float ln0 = sqrtf(vx0 * vx0 + vy0 * vy0 + vz0 * vz0);
        // edge 1
        C = &sC[__float_as_int(A1.w) * 9];
        float vx1 = D1.x - A1.x + c0.w * C[0] + c1.x * C[3] + c1.y * C[6];
        float vy1 = D1.y - A1.y + c0.w * C[1] + c1.x * C[4] + c1.y * C[7];
        float vz1 = D1.z - A1.z + c0.w * C[2] + c1.x * C[5] + c1.y * C[8];
        float ln1 = sqrtf(vx1 * vx1 + vy1 * vy1 + vz1 * vz1);
        // edge 2
        C = &sC[__float_as_int(A2.w) * 9];
        float vx2 = D2.x - A2.x + c1.z * C[0] + c1.w * C[3] + c2.x * C[6];
        float vy2 = D2.y - A2.y + c1.z * C[1] + c1.w * C[4] + c2.x * C[7];
        float vz2 = D2.z - A2.z + c1.z * C[2] + c1.w * C[5] + c2.x * C[8];
        float ln2 = sqrtf(vx2 * vx2 + vy2 * vy2 + vz2 * vz2);
        // edge 3
        C = &sC[__float_as_int(A3.w) * 9];
        float vx3 = D3.x - A3.x + c2.y * C[0] + c2.z * C[3] + c2.w * C[6];
        float vy3 = D3.y - A3.y + c2.y * C[1] + c2.z * C[4] + c2.w * C[7];
        float vz3 = D3.z - A3.z + c2.y * C[2] + c2.z * C[5] + c2.w * C[8];
        float ln3 = sqrtf(vx3 * vx3 + vy3 * vy3 + vz3 * vz3);

        float4* ov = (float4*)out;
        __stcs(&ov[3 * t],     make_float4(vx0, vy0, vz0, vx1));
        __stcs(&ov[3 * t + 1], make_float4(vy1, vz1, vx2, vy2));
        __stcs(&ov[3 * t + 2], make_float4(vz2, vx3, vy3, vz3));
        float4* ol = (float4*)(out + 3 * E);
        __stcs(&ol[t], make_float4(ln0, ln1, ln2, ln3));
    } else {
        // scalar fallback (E not divisible by 4)
        for (long long e = e0; e < e0 + 4 && e < E; e++) {
            long long src, dst;
            if (sI) {
                const long long* p = (const long long*)eidx;
                src = p[e]; dst = p[E + e];
            } else {
                const int* p = (const int*)eidx;
                src = p[e]; dst = p[E + e];
            }
            float4 as = __ldg(&g_atom[src]);
            float4 ad = __ldg(&g_atom[dst]);
            const float* C = &sC[__float_as_int(as.w) * 9];
            float s0 = cshift[3 * e], s1 = cshift[3 * e + 1], s2 = cshift[3 * e + 2];
            float ex = ad.x - as.x + s0 * C[0] + s1 * C[3] + s2 * C[6];
            float ey = ad.y - as.y + s0 * C[1] + s1 * C[4] + s2 * C[7];
            float ez = ad.z - as.z + s0 * C[2] + s1 * C[5] + s2 * C[8];
            out[3 * e] = ex; out[3 * e + 1] = ey; out[3 * e + 2] = ez;
            out[3 * E + e] = sqrtf(ex * ex + ey * ey + ez * ez);
        }
    }
}

// ---------------------------------------------------------------------------
extern "C" void kernel_launch(void* const* d_in, const int* in_sizes, int n_in,
                              void* d_out, int out_size) {
    const float* pos    = (const float*)d_in[0];   // [N_ATOMS, 3]
    const float* cell   = (const float*)d_in[1];   // [NB, 3, 3]
    const float* cshift = (const float*)d_in[2];   // [E, 3]
    const void*  eidx   = d_in[3];                 // [2, E] int32 or int64
    const void*  batch  = d_in[4];                 // [N_ATOMS] int32 or int64
    const float* strain = (const float*)d_in[5];   // [NB, 3, 3]

    int n_atoms = in_sizes[0] / 3;
    long long E = (long long)in_sizes[3] / 2;

    int ablocks = (n_atoms + 255) / 256;
    atom_kernel<<<ablocks, 256>>>(pos, batch, eidx, strain, cell, n_atoms);

    long long egroups = (E + 3) / 4;
    int eblocks = (int)((egroups + 255) / 256);
    edge_kernel<<<eblocks, 256>>>(eidx, cshift, (float*)d_out, E);
}

// round 9
// speedup vs baseline: 1.8970x; 1.0578x over previous
#include <cuda_runtime.h>
#include <math.h>
#include <stdint.h>

#define NB 128
#define NA_MAX 500000

// Scratch (allocation-free: __device__ globals)
__device__ float  g_cell[NB * 9];    // cell + cell @ sym (written by atom block 0)
__device__ float4 g_atom[NA_MAX];    // strained pos + batch (bit-cast)
__device__ int    g_is64;            // 1 if edge_index/batch are int64

// ---------------------------------------------------------------------------
// Kernel 1: per-atom strained position packed with batch into float4.
// Block 0 additionally publishes g_cell and g_is64 for the edge kernel.
// ---------------------------------------------------------------------------
__global__ void __launch_bounds__(256) atom_kernel(
        const float* __restrict__ pos,
        const void*  __restrict__ batch,
        const void*  __restrict__ eidx,
        const float* __restrict__ strain,
        const float* __restrict__ cell,
        int n_atoms) {
    __shared__ float sS[NB * 9];
    __shared__ int s_is64;
    int tid = threadIdx.x;

    // dtype detection: int64 indices (< 2^31, nonneg) have all-zero odd words.
    if (tid == 0) {
        const unsigned* w = (const unsigned*)eidx;
        unsigned any = 0;
#pragma unroll
        for (int i = 0; i < 64; i++) any |= w[2 * i + 1];
        s_is64 = (any == 0u) ? 1 : 0;
    }
    // sym = 0.5 * (strain + strain^T)
    for (int i = tid; i < NB * 9; i += blockDim.x) {
        int b = i / 9, r = (i % 9) / 3, c = i % 3;
        sS[i] = 0.5f * (strain[b * 9 + r * 3 + c] + strain[b * 9 + c * 3 + r]);
    }
    __syncthreads();

    if (blockIdx.x == 0) {
        // cell_new = cell + cell @ sym  (published for edge kernel)
        for (int i = tid; i < NB * 9; i += blockDim.x) {
            int b = i / 9, r = (i % 9) / 3, c = i % 3;
            float acc = cell[i];
#pragma unroll
            for (int k = 0; k < 3; k++)
                acc += cell[b * 9 + r * 3 + k] * sS[b * 9 + k * 3 + c];
            g_cell[i] = acc;
        }
        if (tid == 0) g_is64 = s_is64;
    }

    int i = blockIdx.x * blockDim.x + tid;
    if (i >= n_atoms) return;

    int b = s_is64 ? (int)((const long long*)batch)[i]
                   : ((const int*)batch)[i];

    float px = pos[3 * i], py = pos[3 * i + 1], pz = pos[3 * i + 2];
    const float* S = &sS[b * 9];
    float nx = px + px * S[0] + py * S[3] + pz * S[6];
    float ny = py + px * S[1] + py * S[4] + pz * S[7];
    float nz = pz + px * S[2] + py * S[5] + pz * S[8];
    g_atom[i] = make_float4(nx, ny, nz, __int_as_float(b));
}

// ---------------------------------------------------------------------------
// Index loader: one group of 4 edges -> src/dst as int4 (uniform branch).
// ---------------------------------------------------------------------------
__device__ __forceinline__ void load_idx(bool is64, const void* __restrict__ eidx,
                                         long long E, long long g,
                                         int4& s, int4& d) {
    if (is64) {
        const longlong2* ps = (const longlong2*)eidx;
        longlong2 a = __ldcs(&ps[2 * g]);
        longlong2 b = __ldcs(&ps[2 * g + 1]);
        const longlong2* pd = (const longlong2*)((const long long*)eidx + E);
        longlong2 c = __ldcs(&pd[2 * g]);
        longlong2 dd = __ldcs(&pd[2 * g + 1]);
        s = make_int4((int)a.x, (int)a.y, (int)b.x, (int)b.y);
        d = make_int4((int)c.x, (int)c.y, (int)dd.x, (int)dd.y);
    } else {
        const int4* ps = (const int4*)eidx;
        s = __ldcs(&ps[g]);
        const int4* pd = (const int4*)((const int*)eidx + E);
        d = __ldcs(&pd[g]);
    }
}

// ---------------------------------------------------------------------------
// Kernel 2: edge vectors + lengths. 4 groups (16 edges) per thread with
// software-pipelined index prefetch; per-group body is the proven-fastest
// access pattern (vectorized .cs streams, scalar smem cell lookup, scalars
// only). NO register cap (any cap spills float4 operands).
// ---------------------------------------------------------------------------
__global__ void __launch_bounds__(256) edge_kernel(
        const void*  __restrict__ eidx,
        const float* __restrict__ cshift,
        float*       __restrict__ out,
        long long E) {
    __shared__ float sC[NB * 9];
    __shared__ int sI_s;
    if (threadIdx.x == 0) sI_s = g_is64;
    for (int i = threadIdx.x; i < NB * 9; i += blockDim.x)
        sC[i] = g_cell[i];
    __syncthreads();

    const bool is64 = (sI_s != 0);
    const long long G = E >> 2;          // complete groups of 4

    long long g = (long long)blockIdx.x * 1024 + threadIdx.x;
    int4 sc, dc;
    bool v = (g < G);
    if (v) load_idx(is64, eidx, E, g, sc, dc);

#pragma unroll
    for (int it = 0; it < 4; it++) {
        // prefetch next group's indices (overlaps this group's gathers/compute)
        long long gn = g + 256;
        int4 sn, dn;
        bool vn = (it < 3) && (gn < G);
        if (vn) load_idx(is64, eidx, E, gn, sn, dn);

        if (v) {
            // 8 independent 16B gathers in flight (L2-resident table)
            float4 A0 = __ldg(&g_atom[sc.x]);
            float4 A1 = __ldg(&g_atom[sc.y]);
            float4 A2 = __ldg(&g_atom[sc.z]);
            float4 A3 = __ldg(&g_atom[sc.w]);
            float4 D0 = __ldg(&g_atom[dc.x]);
            float4 D1 = __ldg(&g_atom[dc.y]);
            float4 D2 = __ldg(&g_atom[dc.z]);
            float4 D3 = __ldg(&g_atom[dc.w]);

            const float4* cs4 = (const float4*)cshift;
            float4 c0 = __ldcs(&cs4[3 * g]);
            float4 c1 = __ldcs(&cs4[3 * g + 1]);
            float4 c2 = __ldcs(&cs4[3 * g + 2]);

            // edge 0
            const float* C = &sC[__float_as_int(A0.w) * 9];
            float vx0 = D0.x - A0.x + c0.x * C[0] + c0.y * C[3] + c0.z * C[6];
            float vy0 = D0.y - A0.y + c0.x * C[1] + c0.y * C[4] + c0.z * C[7];
            float vz0 = D0.z - A0.z + c0.x * C[2] + c0.y * C[5] + c0.z * C[8];
            float ln0 = sqrtf(vx0 * vx0 + vy0 * vy0 + vz0 * vz0);
            // edge 1
            C = &sC[__float_as_int(A1.w) * 9];
            float vx1 = D1.x - A1.x + c0.w * C[0] + c1.x * C[3] + c1.y * C[6];
            float vy1 = D1.y - A1.y + c0.w * C[1] + c1.x * C[4] + c1.y * C[7];
            float vz1 = D1.z - A1.z + c0.w * C[2] + c1.x * C[5] + c1.y * C[8];
            float ln1 = sqrtf(vx1 * vx1 + vy1 * vy1 + vz1 * vz1);
            // edge 2
            C = &sC[__float_as_int(A2.w) * 9];
            float vx2 = D2.x - A2.x + c1.z * C[0] + c1.w * C[3] + c2.x * C[6];
            float vy2 = D2.y - A2.y + c1.z * C[1] + c1.w * C[4] + c2.x * C[7];
            float vz2 = D2.z - A2.z + c1.z * C[2] + c1.w * C[5] + c2.x * C[8];
            float ln2 = sqrtf(vx2 * vx2 + vy2 * vy2 + vz2 * vz2);
            // edge 3
            C = &sC[__float_as_int(A3.w) * 9];
            float vx3 = D3.x - A3.x + c2.y * C[0] + c2.z * C[3] + c2.w * C[6];
            float vy3 = D3.y - A3.y + c2.y * C[1] + c2.z * C[4] + c2.w * C[7];
            float vz3 = D3.z - A3.z + c2.y * C[2] + c2.z * C[5] + c2.w * C[8];
            float ln3 = sqrtf(vx3 * vx3 + vy3 * vy3 + vz3 * vz3);

            float4* ov = (float4*)out;
            __stcs(&ov[3 * g],     make_float4(vx0, vy0, vz0, vx1));
            __stcs(&ov[3 * g + 1], make_float4(vy1, vz1, vx2, vy2));
            __stcs(&ov[3 * g + 2], make_float4(vz2, vx3, vy3, vz3));
            if ((E & 3LL) == 0LL) {
                float4* ol = (float4*)(out + 3 * E);
                __stcs(&ol[g], make_float4(ln0, ln1, ln2, ln3));
            } else {
                float* ol = out + 3 * E + 4 * g;
                __stcs(ol, ln0); __stcs(ol + 1, ln1);
                __stcs(ol + 2, ln2); __stcs(ol + 3, ln3);
            }
        }
        g = gn; sc = sn; dc = dn; v = vn;
    }

    // tail: last E & 3 edges, scalar (block 0 only)
    if (blockIdx.x == 0 && threadIdx.x < (int)(E & 3LL)) {
        long long e = (G << 2) + threadIdx.x;
        long long src, dst;
        if (is64) {
            const long long* p = (const long long*)eidx;
            src = p[e]; dst = p[E + e];
        } else {
            const int* p = (const int*)eidx;
            src = p[e]; dst = p[E + e];
        }
        float4 as = __ldg(&g_atom[src]);
        float4 ad = __ldg(&g_atom[dst]);
        const float* C = &sC[__float_as_int(as.w) * 9];
        float s0 = cshift[3 * e], s1 = cshift[3 * e + 1], s2 = cshift[3 * e + 2];
        float ex = ad.x - as.x + s0 * C[0] + s1 * C[3] + s2 * C[6];
        float ey = ad.y - as.y + s0 * C[1] + s1 * C[4] + s2 * C[7];
        float ez = ad.z - as.z + s0 * C[2] + s1 * C[5] + s2 * C[8];
        out[3 * e] = ex; out[3 * e + 1] = ey; out[3 * e + 2] = ez;
        out[3 * E + e] = sqrtf(ex * ex + ey * ey + ez * ez);
    }
}

// ---------------------------------------------------------------------------
extern "C" void kernel_launch(void* const* d_in, const int* in_sizes, int n_in,
                              void* d_out, int out_size) {
    const float* pos    = (const float*)d_in[0];   // [N_ATOMS, 3]
    const float* cell   = (const float*)d_in[1];   // [NB, 3, 3]
    const float* cshift = (const float*)d_in[2];   // [E, 3]
    const void*  eidx   = d_in[3];                 // [2, E] int32 or int64
    const void*  batch  = d_in[4];                 // [N_ATOMS] int32 or int64
    const float* strain = (const float*)d_in[5];   // [NB, 3, 3]

    int n_atoms = in_sizes[0] / 3;
    long long E = (long long)in_sizes[3] / 2;

    int ablocks = (n_atoms + 255) / 256;
    atom_kernel<<<ablocks, 256>>>(pos, batch, eidx, strain, cell, n_atoms);

    long long G = E >> 2;                       // groups of 4 edges
    long long eblocks = (G + 1023) / 1024;      // 4 groups per thread
    if (eblocks < 1) eblocks = 1;
    edge_kernel<<<(unsigned)eblocks, 256>>>(eidx, cshift, (float*)d_out, E);
}

// round 10
// speedup vs baseline: 1.9040x; 1.0037x over previous
#include <cuda_runtime.h>
#include <math.h>
#include <stdint.h>

#define NB 128
#define NA_MAX 500000

// Scratch (allocation-free: __device__ globals)
__device__ float  g_cell[NB * 9];    // cell + cell @ sym (written by atom block 0)
__device__ float4 g_atom[NA_MAX];    // strained pos + batch (bit-cast)
__device__ int    g_is64;            // 1 if edge_index/batch are int64

// ---------------------------------------------------------------------------
// Kernel 1: per-atom strained position packed with batch into float4.
// Block 0 additionally publishes g_cell and g_is64 for the edge kernel.
// ---------------------------------------------------------------------------
__global__ void __launch_bounds__(256) atom_kernel(
        const float* __restrict__ pos,
        const void*  __restrict__ batch,
        const void*  __restrict__ eidx,
        const float* __restrict__ strain,
        const float* __restrict__ cell,
        int n_atoms) {
    __shared__ float sS[NB * 9];
    __shared__ int s_is64;
    int tid = threadIdx.x;

    // dtype detection: int64 indices (< 2^31, nonneg) have all-zero odd words.
    if (tid == 0) {
        const unsigned* w = (const unsigned*)eidx;
        unsigned any = 0;
#pragma unroll
        for (int i = 0; i < 64; i++) any |= w[2 * i + 1];
        s_is64 = (any == 0u) ? 1 : 0;
    }
    // sym = 0.5 * (strain + strain^T)
    for (int i = tid; i < NB * 9; i += blockDim.x) {
        int b = i / 9, r = (i % 9) / 3, c = i % 3;
        sS[i] = 0.5f * (strain[b * 9 + r * 3 + c] + strain[b * 9 + c * 3 + r]);
    }
    __syncthreads();

    if (blockIdx.x == 0) {
        // cell_new = cell + cell @ sym  (published for edge kernel)
        for (int i = tid; i < NB * 9; i += blockDim.x) {
            int b = i / 9, r = (i % 9) / 3, c = i % 3;
            float acc = cell[i];
#pragma unroll
            for (int k = 0; k < 3; k++)
                acc += cell[b * 9 + r * 3 + k] * sS[b * 9 + k * 3 + c];
            g_cell[i] = acc;
        }
        if (tid == 0) g_is64 = s_is64;
    }

    int i = blockIdx.x * blockDim.x + tid;
    if (i >= n_atoms) return;

    int b = s_is64 ? (int)((const long long*)batch)[i]
                   : ((const int*)batch)[i];

    float px = pos[3 * i], py = pos[3 * i + 1], pz = pos[3 * i + 2];
    const float* S = &sS[b * 9];
    float nx = px + px * S[0] + py * S[3] + pz * S[6];
    float ny = py + px * S[1] + py * S[4] + pz * S[7];
    float nz = pz + px * S[2] + py * S[5] + pz * S[8];
    g_atom[i] = make_float4(nx, ny, nz, __int_as_float(b));
}

// ---------------------------------------------------------------------------
// Index loader: one group of 4 edges -> src/dst as int4 (uniform branch).
// ---------------------------------------------------------------------------
__device__ __forceinline__ void load_idx(bool is64, const void* __restrict__ eidx,
                                         long long E, long long g,
                                         int4& s, int4& d) {
    if (is64) {
        const longlong2* ps = (const longlong2*)eidx;
        longlong2 a = __ldcs(&ps[2 * g]);
        longlong2 b = __ldcs(&ps[2 * g + 1]);
        const longlong2* pd = (const longlong2*)((const long long*)eidx + E);
        longlong2 c = __ldcs(&pd[2 * g]);
        longlong2 dd = __ldcs(&pd[2 * g + 1]);
        s = make_int4((int)a.x, (int)a.y, (int)b.x, (int)b.y);
        d = make_int4((int)c.x, (int)c.y, (int)dd.x, (int)dd.y);
    } else {
        const int4* ps = (const int4*)eidx;
        s = __ldcs(&ps[g]);
        const int4* pd = (const int4*)((const int*)eidx + E);
        d = __ldcs(&pd[g]);
    }
}

// ---------------------------------------------------------------------------
// Kernel 2: edge vectors + lengths. 4 groups (16 edges) per thread with
// software-pipelined index prefetch; per-group body is the proven-fastest
// access pattern (vectorized .cs streams, scalar smem cell lookup, scalars
// only). NO register cap (any cap spills float4 operands).
// ---------------------------------------------------------------------------
__global__ void __launch_bounds__(256) edge_kernel(
        const void*  __restrict__ eidx,
        const float* __restrict__ cshift,
        float*       __restrict__ out,
        long long E) {
    __shared__ float sC[NB * 9];
    __shared__ int sI_s;
    if (threadIdx.x == 0) sI_s = g_is64;
    for (int i = threadIdx.x; i < NB * 9; i += blockDim.x)
        sC[i] = g_cell[i];
    __syncthreads();

    const bool is64 = (sI_s != 0);
    const long long G = E >> 2;          // complete groups of 4

    long long g = (long long)blockIdx.x * 1024 + threadIdx.x;
    int4 sc, dc;
    bool v = (g < G);
    if (v) load_idx(is64, eidx, E, g, sc, dc);

#pragma unroll
    for (int it = 0; it < 4; it++) {
        // prefetch next group's indices (overlaps this group's gathers/compute)
        long long gn = g + 256;
        int4 sn, dn;
        bool vn = (it < 3) && (gn < G);
        if (vn) load_idx(is64, eidx, E, gn, sn, dn);

        if (v) {
            // 8 independent 16B gathers in flight (L2-resident table)
            float4 A0 = __ldg(&g_atom[sc.x]);
            float4 A1 = __ldg(&g_atom[sc.y]);
            float4 A2 = __ldg(&g_atom[sc.z]);
            float4 A3 = __ldg(&g_atom[sc.w]);
            float4 D0 = __ldg(&g_atom[dc.x]);
            float4 D1 = __ldg(&g_atom[dc.y]);
            float4 D2 = __ldg(&g_atom[dc.z]);
            float4 D3 = __ldg(&g_atom[dc.w]);

            const float4* cs4 = (const float4*)cshift;
            float4 c0 = __ldcs(&cs4[3 * g]);
            float4 c1 = __ldcs(&cs4[3 * g + 1]);
            float4 c2 = __ldcs(&cs4[3 * g + 2]);

            // edge 0
            const float* C = &sC[__float_as_int(A0.w) * 9];
            float vx0 = D0.x - A0.x + c0.x * C[0] + c0.y * C[3] + c0.z * C[6];
            float vy0 = D0.y - A0.y + c0.x * C[1] + c0.y * C[4] + c0.z * C[7];
            float vz0 = D0.z - A0.z + c0.x * C[2] + c0.y * C[5] + c0.z * C[8];
            float ln0 = sqrtf(vx0 * vx0 + vy0 * vy0 + vz0 * vz0);
            // edge 1
            C = &sC[__float_as_int(A1.w) * 9];
            float vx1 = D1.x - A1.x + c0.w * C[0] + c1.x * C[3] + c1.y * C[6];
            float vy1 = D1.y - A1.y + c0.w * C[1] + c1.x * C[4] + c1.y * C[7];
            float vz1 = D1.z - A1.z + c0.w * C[2] + c1.x * C[5] + c1.y * C[8];
            float ln1 = sqrtf(vx1 * vx1 + vy1 * vy1 + vz1 * vz1);
            // edge 2
            C = &sC[__float_as_int(A2.w) * 9];
            float vx2 = D2.x - A2.x + c1.z * C[0] + c1.w * C[3] + c2.x * C[6];
            float vy2 = D2.y - A2.y + c1.z * C[1] + c1.w * C[4] + c2.x * C[7];
            float vz2 = D2.z - A2.z + c1.z * C[2] + c1.w * C[5] + c2.x * C[8];
            float ln2 = sqrtf(vx2 * vx2 + vy2 * vy2 + vz2 * vz2);
            // edge 3
            C = &sC[__float_as_int(A3.w) * 9];
            float vx3 = D3.x - A3.x + c2.y * C[0] + c2.z * C[3] + c2.w * C[6];
            float vy3 = D3.y - A3.y + c2.y * C[1] + c2.z * C[4] + c2.w * C[7];
            float vz3 = D3.z - A3.z + c2.y * C[2] + c2.z * C[5] + c2.w * C[8];
            float ln3 = sqrtf(vx3 * vx3 + vy3 * vy3 + vz3 * vz3);

            float4* ov = (float4*)out;
            __stcs(&ov[3 * g],     make_float4(vx0, vy0, vz0, vx1));
            __stcs(&ov[3 * g + 1], make_float4(vy1, vz1, vx2, vy2));
            __stcs(&ov[3 * g + 2], make_float4(vz2, vx3, vy3, vz3));
            if ((E & 3LL) == 0LL) {
                float4* ol = (float4*)(out + 3 * E);
                __stcs(&ol[g], make_float4(ln0, ln1, ln2, ln3));
            } else {
                float* ol = out + 3 * E + 4 * g;
                __stcs(ol, ln0); __stcs(ol + 1, ln1);
                __stcs(ol + 2, ln2); __stcs(ol + 3, ln3);
            }
        }
        g = gn; sc = sn; dc = dn; v = vn;
    }

    // tail: last E & 3 edges, scalar (block 0 only)
    if (blockIdx.x == 0 && threadIdx.x < (int)(E & 3LL)) {
        long long e = (G << 2) + threadIdx.x;
        long long src, dst;
        if (is64) {
            const long long* p = (const long long*)eidx;
            src = p[e]; dst = p[E + e];
        } else {
            const int* p = (const int*)eidx;
            src = p[e]; dst = p[E + e];
        }
        float4 as = __ldg(&g_atom[src]);
        float4 ad = __ldg(&g_atom[dst]);
        const float* C = &sC[__float_as_int(as.w) * 9];
        float s0 = cshift[3 * e], s1 = cshift[3 * e + 1], s2 = cshift[3 * e + 2];
        float ex = ad.x - as.x + s0 * C[0] + s1 * C[3] + s2 * C[6];
        float ey = ad.y - as.y + s0 * C[1] + s1 * C[4] + s2 * C[7];
        float ez = ad.z - as.z + s0 * C[2] + s1 * C[5] + s2 * C[8];
        out[3 * e] = ex; out[3 * e + 1] = ey; out[3 * e + 2] = ez;
        out[3 * E + e] = sqrtf(ex * ex + ey * ey + ez * ez);
    }
}

// ---------------------------------------------------------------------------
extern "C" void kernel_launch(void* const* d_in, const int* in_sizes, int n_in,
                              void* d_out, int out_size) {
    const float* pos    = (const float*)d_in[0];   // [N_ATOMS, 3]
    const float* cell   = (const float*)d_in[1];   // [NB, 3, 3]
    const float* cshift = (const float*)d_in[2];   // [E, 3]
    const void*  eidx   = d_in[3];                 // [2, E] int32 or int64
    const void*  batch  = d_in[4];                 // [N_ATOMS] int32 or int64
    const float* strain = (const float*)d_in[5];   // [NB, 3, 3]

    int n_atoms = in_sizes[0] / 3;
    long long E = (long long)in_sizes[3] / 2;

    int ablocks = (n_atoms + 255) / 256;
    atom_kernel<<<ablocks, 256>>>(pos, batch, eidx, strain, cell, n_atoms);

    long long G = E >> 2;                       // groups of 4 edges
    long long eblocks = (G + 1023) / 1024;      // 4 groups per thread
    if (eblocks < 1) eblocks = 1;
    edge_kernel<<<(unsigned)eblocks, 256>>>(eidx, cshift, (float*)d_out, E);
}